// round 13
// baseline (speedup 1.0000x reference)
#include <cuda_runtime.h>
#include <math.h>
#include <stdint.h>

// ---------------------------------------------------------------------------
// CNN-LSTM: emb-gather -> conv1d(K=5,VALID) -> relu -> maxpool(4) -> LSTM -> FC
// B=64 L=4096 VOCAB=20000 E=128 F=64 K=5 P=4 H=128 C=2
//
//   K0: transpose conv_w -> [e][k*64+f]
//   K1: proj[v][k][f] = emb[v] . conv_w[f,:,k]   (20000x320 table, L2-resident)
//   K2: conv+relu+pool via 20 L2-hit gathers per pooled output
//   K3: xg = pooled @ w_ih^T + biases   (2 cols reg-resident, 4-row blocks)
//   K4: persistent LSTM, 2-CTA CLUSTER per batch, ALL weights in registers,
//       DSMEM h-exchange with mbarrier handshake, double-buffered h,
//       quad-lane gate shuffle, ONE __syncthreads per step
// ---------------------------------------------------------------------------

using u64 = unsigned long long;
#define DI __device__ __forceinline__

namespace {
constexpr int B_ = 64, L_ = 4096, E_ = 128, F_ = 64, K_ = 5, H_ = 128;
constexpr int VOCAB_ = 20000;
constexpr int FK_ = K_ * F_;     // 320
constexpr int LP_ = 1023;        // pooled sequence length (4092/4)
constexpr int G_ = 4 * H_;       // 512 gate rows
constexpr int M_ = B_ * LP_;     // 65472 pooled rows
}

// scratch (device globals -- no runtime allocation allowed)
__device__ float g_cwt[E_ * FK_];        // transposed conv weights
__device__ float g_proj[VOCAB_ * FK_];   // 25.6 MB token->conv projection table
__device__ float g_pooled[M_ * F_];      // 16.8 MB pooled features
__device__ float g_xg[M_ * G_];          // 134 MB precomputed gate inputs

// ---- packed f32x2 helpers (Blackwell FFMA2) -------------------------------
DI void fma2(u64 &acc, u64 a, u64 b) {
    asm("fma.rn.f32x2 %0, %1, %2, %0;" : "+l"(acc) : "l"(a), "l"(b));
}
DI u64 pk2(float lo, float hi) {
    u64 r;
    asm("mov.b64 %0, {%1, %2};" : "=l"(r) : "f"(lo), "f"(hi));
    return r;
}
DI float sum2(u64 v) {
    float lo, hi;
    asm("mov.b64 {%0, %1}, %2;" : "=f"(lo), "=f"(hi) : "l"(v));
    return lo + hi;
}

DI float sigf(float x) { return 1.0f / (1.0f + __expf(-x)); }

// ---- cluster / mbarrier asm helpers ---------------------------------------
DI uint32_t smem_u32(const void* p) {
    uint32_t a;
    asm("{.reg .u64 t; cvta.to.shared.u64 t, %1; cvt.u32.u64 %0, t;}"
        : "=r"(a) : "l"(p));
    return a;
}
DI uint32_t mapa_u32(uint32_t addr, uint32_t rank) {
    uint32_t d;
    asm("mapa.shared::cluster.u32 %0, %1, %2;" : "=r"(d) : "r"(addr), "r"(rank));
    return d;
}
DI void st_cluster_f32(uint32_t addr, float v) {
    asm volatile("st.shared::cluster.f32 [%0], %1;" :: "r"(addr), "f"(v) : "memory");
}
DI void mbar_init(uint32_t addr, uint32_t cnt) {
    asm volatile("mbarrier.init.shared.b64 [%0], %1;" :: "r"(addr), "r"(cnt) : "memory");
}
DI void mbar_arrive_cluster(uint32_t remote_addr) {
    asm volatile("mbarrier.arrive.release.cluster.shared::cluster.b64 _, [%0];"
                 :: "r"(remote_addr) : "memory");
}
DI void mbar_wait_parity_cluster(uint32_t addr, uint32_t parity) {
    asm volatile(
        "{\n\t"
        ".reg .pred P;\n\t"
        "W_%=:\n\t"
        "mbarrier.try_wait.parity.acquire.cluster.shared::cta.b64 P, [%0], %1, 0x989680;\n\t"
        "@P bra D_%=;\n\t"
        "bra W_%=;\n\t"
        "D_%=:\n\t"
        "}"
        :: "r"(addr), "r"(parity) : "memory");
}
DI void cluster_sync_() {
    asm volatile("barrier.cluster.arrive.aligned;" ::: "memory");
    asm volatile("barrier.cluster.wait.aligned;" ::: "memory");
}

// ---- K0: transpose conv_w [F,E,K] -> g_cwt[e][k*64+f] ---------------------
__global__ void k_wt(const float* __restrict__ cw) {
    int i = blockIdx.x * 256 + threadIdx.x;
    if (i < E_ * FK_) {
        int e = i / FK_, col = i % FK_;
        int k = col >> 6, f = col & 63;
        g_cwt[i] = cw[(f * E_ + e) * K_ + k];
    }
}

// ---- K1: proj table GEMM. CTA = 32 vocab rows staged in smem --------------
__global__ void __launch_bounds__(320) k_proj(const float* __restrict__ emb) {
    __shared__ __align__(16) float es[32 * E_];   // 16 KB
    int c = threadIdx.x;
    u64 w[64];
#pragma unroll
    for (int j = 0; j < 64; j++)
        w[j] = pk2(g_cwt[(2 * j) * FK_ + c], g_cwt[(2 * j + 1) * FK_ + c]);
    int v0 = blockIdx.x * 32;
    const float4* src = (const float4*)(emb + v0 * E_);
    for (int i = threadIdx.x; i < 32 * E_ / 4; i += 320)
        ((float4*)es)[i] = src[i];
    __syncthreads();
#pragma unroll 1
    for (int vi = 0; vi < 32; vi++) {
        const ulonglong2* h4 = (const ulonglong2*)(es + vi * E_);
        u64 a0 = 0ull, a1 = 0ull;
#pragma unroll
        for (int j = 0; j < 32; j++) {
            ulonglong2 h = h4[j];
            fma2(a0, h.x, w[2 * j]);
            fma2(a1, h.y, w[2 * j + 1]);
        }
        g_proj[(v0 + vi) * FK_ + c] = sum2(a0) + sum2(a1);
    }
}

// ---- K2: conv + relu + maxpool. thread = (b, pooled pos p, feature f) -----
__global__ void k_convpool(const int* __restrict__ x, const float* __restrict__ cb) {
    int f = threadIdx.x & 63;
    int p = blockIdx.x * 4 + (threadIdx.x >> 6);
    int b = blockIdx.y;
    if (p >= LP_) return;
    const int* xb = x + b * L_;
    int s0 = p * 4;
    int tok[8];
#pragma unroll
    for (int i = 0; i < 8; i++) tok[i] = __ldg(xb + s0 + i);
    float a0 = 0.f, a1 = 0.f, a2 = 0.f, a3 = 0.f;
#pragma unroll
    for (int k = 0; k < K_; k++) {
        const float* pr = g_proj + k * 64 + f;
        a0 += __ldg(pr + tok[k + 0] * FK_);
        a1 += __ldg(pr + tok[k + 1] * FK_);
        a2 += __ldg(pr + tok[k + 2] * FK_);
        a3 += __ldg(pr + tok[k + 3] * FK_);
    }
    float bias = __ldg(cb + f);
    float m = fmaxf(fmaxf(a0, a1), fmaxf(a2, a3)) + bias;
    g_pooled[(b * LP_ + p) * F_ + f] = fmaxf(m, 0.0f);  // relu(max) == max(relu)
}

// ---- K3: xg = pooled @ w_ih^T + (b_ih + b_hh)  [R11 design: best measured] -
// CTA = 256 threads covering ALL 512 gate cols (2 cols/thread: t and t+256),
// 64 pooled rows staged in smem. Each LDS.128 broadcast feeds 4 FFMA2.
__global__ void __launch_bounds__(256) k_xgate(const float* __restrict__ wih,
                                               const float* __restrict__ bih,
                                               const float* __restrict__ bhh) {
    __shared__ __align__(16) float ps[64 * F_];   // 16 KB
    int t = threadIdx.x;
    u64 w0[32], w1[32];
    const u64* wr0 = (const u64*)(wih + t * F_);
    const u64* wr1 = (const u64*)(wih + (t + 256) * F_);
#pragma unroll
    for (int j = 0; j < 32; j++) { w0[j] = wr0[j]; w1[j] = wr1[j]; }
    float b0 = __ldg(bih + t) + __ldg(bhh + t);
    float b1 = __ldg(bih + t + 256) + __ldg(bhh + t + 256);
    int row0 = blockIdx.x * 64;
    const float4* src = (const float4*)(g_pooled + row0 * F_);
#pragma unroll
    for (int i = 0; i < 4; i++) ((float4*)ps)[t + i * 256] = src[t + i * 256];
    __syncthreads();
#pragma unroll 1
    for (int r = 0; r < 64; r += 4) {
        const ulonglong2* p0 = (const ulonglong2*)(ps + (r + 0) * F_);
        const ulonglong2* p1 = (const ulonglong2*)(ps + (r + 1) * F_);
        const ulonglong2* p2 = (const ulonglong2*)(ps + (r + 2) * F_);
        const ulonglong2* p3 = (const ulonglong2*)(ps + (r + 3) * F_);
        u64 a0A = 0ull, a1A = 0ull, a2A = 0ull, a3A = 0ull;
        u64 a0B = 0ull, a1B = 0ull, a2B = 0ull, a3B = 0ull;
#pragma unroll
        for (int j = 0; j < 16; j++) {
            u64 wl0 = w0[2 * j], wh0 = w0[2 * j + 1];
            u64 wl1 = w1[2 * j], wh1 = w1[2 * j + 1];
            ulonglong2 h0 = p0[j], h1 = p1[j], h2 = p2[j], h3 = p3[j];
            fma2(a0A, h0.x, wl0); fma2(a0A, h0.y, wh0);
            fma2(a0B, h0.x, wl1); fma2(a0B, h0.y, wh1);
            fma2(a1A, h1.x, wl0); fma2(a1A, h1.y, wh0);
            fma2(a1B, h1.x, wl1); fma2(a1B, h1.y, wh1);
            fma2(a2A, h2.x, wl0); fma2(a2A, h2.y, wh0);
            fma2(a2B, h2.x, wl1); fma2(a2B, h2.y, wh1);
            fma2(a3A, h3.x, wl0); fma2(a3A, h3.y, wh0);
            fma2(a3B, h3.x, wl1); fma2(a3B, h3.y, wh1);
        }
        float* dst = g_xg + (size_t)(row0 + r) * G_ + t;
        dst[0 * G_]       = sum2(a0A) + b0;
        dst[0 * G_ + 256] = sum2(a0B) + b1;
        dst[1 * G_]       = sum2(a1A) + b0;
        dst[1 * G_ + 256] = sum2(a1B) + b1;
        dst[2 * G_]       = sum2(a2A) + b0;
        dst[2 * G_ + 256] = sum2(a2B) + b1;
        dst[3 * G_]       = sum2(a3A) + b0;
        dst[3 * G_ + 256] = sum2(a3B) + b1;
    }
}

// ---- K4: cluster LSTM. 2 CTAs per batch, 256 threads each, 1 gate row per
// thread with the FULL weight row in registers (64 u64). CTA rank r owns gate
// rows {gate*128 + r*64 + e : e in [0,64)}. Lane quad layout: 4 consecutive
// lanes = gates (i,f,g,o) of one element e -> combine via 3 shuffles.
// h exchanged per step: local STS + st.shared::cluster into peer, signaled by
// mbarrier (count=64, release/acquire cluster scope). h double-buffered so the
// peer running one step ahead never clobbers a buffer being read.
__global__ void __launch_bounds__(256, 1) __cluster_dims__(2, 1, 1)
k_lstm(const float* __restrict__ whh, const float* __restrict__ fcw,
       const float* __restrict__ fcb, float* __restrict__ out) {
    __shared__ __align__(16) float hs0[H_];   // h buffer, even steps write here
    __shared__ __align__(16) float hs1[H_];   // h buffer, odd steps write here
    __shared__ __align__(8) u64 mbar[1];

    int t = threadIdx.x;
    uint32_t rank;
    asm("mov.u32 %0, %%cluster_ctarank;" : "=r"(rank));
    int b = blockIdx.x >> 1;
    int l = t & 31;
    int e = (t >> 5) * 8 + (l >> 2);   // element 0..63 (this CTA's slice)
    int gate = l & 3;                  // 0=i 1=f 2=g 3=o
    int row = gate * H_ + (int)rank * 64 + e;   // global gate row
    bool writer = (gate == 0);

    // full weight row in registers
    u64 wr[64];
    const u64* wp = (const u64*)(whh + (size_t)row * H_);
#pragma unroll
    for (int j = 0; j < 64; j++) wr[j] = wp[j];

    // init h buffers + mbarrier
    if (t < H_) { hs0[t] = 0.0f; hs1[t] = 0.0f; }
    uint32_t mb = smem_u32(mbar);
    if (t == 0) mbar_init(mb, 64);
    __syncthreads();
    cluster_sync_();   // mbar init + zeroed h visible before any remote traffic

    // remote addresses of my h slot in the peer's buffers
    int slot = (int)rank * 64 + e;
    uint32_t peer = rank ^ 1u;
    uint32_t r_hs0 = mapa_u32(smem_u32(hs0 + slot), peer);
    uint32_t r_hs1 = mapa_u32(smem_u32(hs1 + slot), peer);
    uint32_t r_mb  = mapa_u32(mb, peer);

    const float* xgb = g_xg + (size_t)b * (LP_ * G_) + row;
    float x0 = __ldg(xgb);
    float x1 = __ldg(xgb + G_);
    float c = 0.0f;

#pragma unroll 1
    for (int p = 0; p < LP_; p++) {
        // prefetch xg two steps ahead
        int pn = (p + 2 < LP_) ? p + 2 : LP_ - 1;
        float x2 = __ldg(xgb + (size_t)pn * G_);

        // wait for peer's h slice of step p-1 (phase p-1)
        if (p > 0) mbar_wait_parity_cluster(mb, (uint32_t)((p - 1) & 1));

        // GEMV over previous h: read buffer (p-1)&1  (p=0 -> hs1 = zeros)
        const ulonglong2* h4 =
            (const ulonglong2*)((p & 1) ? hs0 : hs1);
        u64 a0 = 0ull, a1 = 0ull, a2 = 0ull, a3 = 0ull;
#pragma unroll
        for (int j = 0; j < 8; j++) {
            ulonglong2 ha = h4[2 * j], hb = h4[2 * j + 1];
            fma2(a0, ha.x, wr[4 * j]);
            fma2(a1, ha.y, wr[4 * j + 1]);
            fma2(a2, hb.x, wr[4 * j + 2]);
            fma2(a3, hb.y, wr[4 * j + 3]);
        }
#pragma unroll
        for (int j = 8; j < 16; j++) {
            ulonglong2 ha = h4[2 * j], hb = h4[2 * j + 1];
            fma2(a0, ha.x, wr[4 * j]);
            fma2(a1, ha.y, wr[4 * j + 1]);
            fma2(a2, hb.x, wr[4 * j + 2]);
            fma2(a3, hb.y, wr[4 * j + 3]);
        }
        float pre = (sum2(a0) + sum2(a1)) + (sum2(a2) + sum2(a3)) + x0;
        x0 = x1; x1 = x2;

        // activation: sigmoid for i,f,o; tanh for g (= 2*sig(2x)-1)
        float q  = (gate == 2) ? (pre + pre) : pre;
        float s  = sigf(q);
        float act = (gate == 2) ? (2.0f * s - 1.0f) : s;

        // gather quad: lane+1=f, lane+2=g, lane+3=o (valid on gate==0 lanes)
        float vf = __shfl_down_sync(0xffffffffu, act, 1);
        float vg = __shfl_down_sync(0xffffffffu, act, 2);
        float vo = __shfl_down_sync(0xffffffffu, act, 3);

        if (writer) {
            c = vf * c + act * vg;
            float tc = 2.0f * sigf(c + c) - 1.0f;   // tanh(c)
            float h = vo * tc;
            if (p & 1) { hs1[slot] = h; st_cluster_f32(r_hs1, h); }
            else       { hs0[slot] = h; st_cluster_f32(r_hs0, h); }
            mbar_arrive_cluster(r_mb);   // release: remote store visible
        }
        __syncthreads();                 // local h slice visible to all warps
    }

    // final h lives in buffer (LP_-1)&1 == 0; wait for peer's final slice
    mbar_wait_parity_cluster(mb, (uint32_t)((LP_ - 1) & 1));

    // final FC (rank 0 only): out[b][cc] = h . fc_w[cc] + fc_b[cc]
    if (rank == 0 && t < 64) {
        int cc = t >> 5, lane = t & 31;
        float s = 0.0f;
#pragma unroll
        for (int u = 0; u < 4; u++)
            s += hs0[lane + u * 32] * __ldg(fcw + cc * H_ + lane + u * 32);
#pragma unroll
        for (int off = 16; off; off >>= 1) s += __shfl_down_sync(0xffffffffu, s, off);
        if (lane == 0) out[b * 2 + cc] = s + __ldg(fcb + cc);
    }
    // keep the cluster alive until both CTAs are done with remote traffic
    cluster_sync_();
}

// ---------------------------------------------------------------------------
extern "C" void kernel_launch(void* const* d_in, const int* in_sizes, int n_in,
                              void* d_out, int out_size) {
    const int*   x   = (const int*)d_in[0];
    const float* emb = (const float*)d_in[1];
    const float* cw  = (const float*)d_in[2];
    const float* cb  = (const float*)d_in[3];
    const float* wih = (const float*)d_in[4];
    const float* whh = (const float*)d_in[5];
    const float* bih = (const float*)d_in[6];
    const float* bhh = (const float*)d_in[7];
    const float* fcw = (const float*)d_in[8];
    const float* fcb = (const float*)d_in[9];
    float* out = (float*)d_out;

    k_wt<<<(E_ * FK_ + 255) / 256, 256>>>(cw);
    k_proj<<<VOCAB_ / 32, 320>>>(emb);
    k_convpool<<<dim3((LP_ + 3) / 4, B_), 256>>>(x, cb);
    k_xgate<<<M_ / 64, 256>>>(wih, bih, bhh);
    k_lstm<<<2 * B_, 256>>>(whh, fcw, fcb, out);
}